// round 11
// baseline (speedup 1.0000x reference)
#include <cuda_runtime.h>
#include <cuda_fp16.h>
#include <math.h>
#include <stdint.h>

// Problem constants
#define S_TOK 4096
#define DIM   1024
#define NEXP  8
#define HID   4096
#define NSCORES (NEXP * S_TOK)

// ---------------- device scratch ----------------
__device__ float g_scores[NSCORES];
__device__ float g_thresh;
__device__ int   g_cnt[NEXP];
__device__ int   g_rows[NEXP * S_TOK];
__device__ float g_w[NEXP * S_TOK];
__device__ int   g_pos[NSCORES];
__device__ __half g_xh[(size_t)S_TOK * DIM];                     // fp16 x
__device__ unsigned g_w1p[(size_t)NEXP * (DIM / 2) * HID];       // fp16 k-pair packed
__device__ unsigned g_w2p[(size_t)NEXP * (HID / 2) * DIM];
__device__ __half g_hidden[(size_t)NEXP * S_TOK * HID];          // fp16
__device__ float g_y[(size_t)NEXP * S_TOK * DIM];

__device__ __forceinline__ unsigned pack2(float lo, float hi) {
    __half2 h = __floats2half2_rn(lo, hi);
    return *reinterpret_cast<unsigned*>(&h);
}

// ---------------- prep: fp32 -> fp16 conversions ----------------
__global__ void convert_x_kernel(const float* __restrict__ x) {
    size_t idx = (size_t)blockIdx.x * blockDim.x + threadIdx.x;   // one per 8 floats
    size_t i8 = idx * 8;
    float4 a = *(const float4*)(x + i8);
    float4 b = *(const float4*)(x + i8 + 4);
    uint4 o;
    o.x = pack2(a.x, a.y); o.y = pack2(a.z, a.w);
    o.z = pack2(b.x, b.y); o.w = pack2(b.z, b.w);
    *(uint4*)&g_xh[i8] = o;
}

// w [E][K][N] fp32 -> wp [E][K/2][N] uint32 (halves k=2kp,2kp+1)
__global__ void pack_w_kernel(const float* __restrict__ w, unsigned* __restrict__ wp,
                              int K, int N) {
    size_t idx = (size_t)blockIdx.x * blockDim.x + threadIdx.x;   // one per 4 cols
    int nq = (int)(idx % (N / 4)) * 4;
    int kp = (int)((idx / (N / 4)) % (K / 2));
    int e  = (int)(idx / ((size_t)(N / 4) * (K / 2)));
    const float* s0 = w + ((size_t)e * K + 2 * kp) * N + nq;
    float4 r0 = *(const float4*)s0;
    float4 r1 = *(const float4*)(s0 + N);
    uint4 o;
    o.x = pack2(r0.x, r1.x); o.y = pack2(r0.y, r1.y);
    o.z = pack2(r0.z, r1.z); o.w = pack2(r0.w, r1.w);
    *(uint4*)&wp[((size_t)e * (K / 2) + kp) * N + nq] = o;
}

// ---------------- router (exact fp32) ----------------
__global__ void router_kernel(const float* __restrict__ x,
                              const float* __restrict__ gw,
                              const float* __restrict__ eb) {
    int s = blockIdx.x;
    int warp = threadIdx.x >> 5, lane = threadIdx.x & 31;
    const float* xs = x + (size_t)s * DIM;
    const float* g  = gw + (size_t)warp * DIM;
    float acc = 0.f;
    for (int i = lane; i < DIM; i += 32) acc += xs[i] * g[i];
    #pragma unroll
    for (int o = 16; o; o >>= 1) acc += __shfl_xor_sync(0xFFFFFFFFu, acc, o);
    __shared__ float l[NEXP];
    if (lane == 0) l[warp] = acc + eb[warp];
    __syncthreads();
    if (threadIdx.x < NEXP) {
        float m = l[0];
        #pragma unroll
        for (int e = 1; e < NEXP; e++) m = fmaxf(m, l[e]);
        float sum = 0.f;
        #pragma unroll
        for (int e = 0; e < NEXP; e++) sum += expf(l[e] - m);
        g_scores[threadIdx.x * S_TOK + s] = expf(l[threadIdx.x] - m) / sum;
    }
}

// ---------------- exact global top-k threshold (radix select) ----------------
__global__ void topk_kernel(const int* __restrict__ cap) {
    __shared__ int hist[256];
    __shared__ unsigned sh_prefix;
    __shared__ int sh_k;
    if (threadIdx.x < NEXP) g_cnt[threadIdx.x] = 0;
    int k = S_TOK * cap[0];
    if (k < 1) k = 1;
    if (k > NSCORES) k = NSCORES;
    unsigned prefix = 0, mask = 0;
    int kk = k;
    for (int shift = 24; shift >= 0; shift -= 8) {
        for (int i = threadIdx.x; i < 256; i += blockDim.x) hist[i] = 0;
        __syncthreads();
        for (int i = threadIdx.x; i < NSCORES; i += blockDim.x) {
            unsigned u = __float_as_uint(g_scores[i]);
            if ((u & mask) == prefix) atomicAdd(&hist[(u >> shift) & 255], 1);
        }
        __syncthreads();
        if (threadIdx.x == 0) {
            int rem = kk, b = 255;
            for (; b >= 0; --b) {
                if (rem <= hist[b]) break;
                rem -= hist[b];
            }
            if (b < 0) b = 0;
            sh_prefix = prefix | ((unsigned)b << shift);
            sh_k = rem;
        }
        __syncthreads();
        prefix = sh_prefix;
        kk = sh_k;
        mask |= (0xFFu << shift);
        __syncthreads();
    }
    if (threadIdx.x == 0) g_thresh = __uint_as_float(prefix);
}

__global__ void build_kernel() {
    int i = blockIdx.x * blockDim.x + threadIdx.x;
    if (i >= NSCORES) return;
    float sc = g_scores[i];
    int e = i >> 12;
    int p = -1;
    if (sc >= g_thresh) {
        int r = atomicAdd(&g_cnt[e], 1);
        g_rows[e * S_TOK + r] = i & (S_TOK - 1);
        g_w[e * S_TOK + r]    = sc;
        p = r;
    }
    g_pos[i] = p;
}

// ------- fp16 mma GEMM: 128 threads, warp tile 64x64, cp.async 4-stage ------
#define BM 128
#define BN 128
#define BK 16
#define NTHR 128
#define STAGES 4
#define ASTRW 12                               // A row stride (words)
#define BSTRW 136                              // B row stride (words)
#define A_WORDS (BM * ASTRW)                   // 1536
#define B_WORDS (8 * BSTRW)                    // 1088
#define STAGE_WORDS (A_WORDS + B_WORDS)        // 2624
#define STAGE_BYTES (STAGE_WORDS * 4)          // 10496

#define CP16(dst_s, src_g) \
    asm volatile("cp.async.cg.shared.global [%0], [%1], 16;" :: "r"(dst_s), "l"(src_g) : "memory")
#define CP_COMMIT() asm volatile("cp.async.commit_group;" ::: "memory")
#define CP_WAIT2()  asm volatile("cp.async.wait_group 2;" ::: "memory")

__device__ __forceinline__ void mma_f16(float* c, const unsigned* a, const unsigned* b) {
    asm volatile("mma.sync.aligned.m16n8k16.row.col.f32.f16.f16.f32 "
        "{%0,%1,%2,%3}, {%4,%5,%6,%7}, {%8,%9}, {%0,%1,%2,%3};"
        : "+f"(c[0]), "+f"(c[1]), "+f"(c[2]), "+f"(c[3])
        : "r"(a[0]), "r"(a[1]), "r"(a[2]), "r"(a[3]), "r"(b[0]), "r"(b[1]));
}
__device__ __forceinline__ uint32_t smem_u32(const void* p) {
    uint32_t a;
    asm("{ .reg .u64 t; cvta.to.shared.u64 t, %1; cvt.u32.u64 %0, t; }" : "=r"(a) : "l"(p));
    return a;
}

// warp tile 64x64: 4 m-tiles x 8 n-tiles of m16n8k16
__device__ __forceinline__ void compute_stage(const unsigned* stg,
                                              int wm, int wn, int gid, int tig,
                                              float acc[4][8][4]) {
    const unsigned* As = stg;
    const unsigned* Bs = stg + A_WORDS;
    unsigned af[4][4], bf[8][2];
    #pragma unroll
    for (int mt = 0; mt < 4; mt++) {
        int r = wm + mt * 16 + gid;
        af[mt][0] = As[r * ASTRW + tig];
        af[mt][1] = As[(r + 8) * ASTRW + tig];
        af[mt][2] = As[r * ASTRW + tig + 4];
        af[mt][3] = As[(r + 8) * ASTRW + tig + 4];
    }
    #pragma unroll
    for (int nt = 0; nt < 8; nt++) {
        int n = wn + nt * 8 + gid;
        bf[nt][0] = Bs[tig * BSTRW + n];
        bf[nt][1] = Bs[(tig + 4) * BSTRW + n];
    }
    #pragma unroll
    for (int mt = 0; mt < 4; mt++)
        #pragma unroll
        for (int nt = 0; nt < 8; nt++)
            mma_f16(acc[mt][nt], af[mt], bf[nt]);
}

// staging: thread t: A row t (16 halves = 2 cp), B kp=t>>4, nq=(t&15)*8 (2 cp)
#define STAGE_CP(slot, k0, aSrcH, bSrcW, ldbW, aDstB, bDstB, sbase)                     \
    do {                                                                                \
        uint32_t so_ = (sbase) + (uint32_t)(slot) * STAGE_BYTES;                        \
        const __half* as_ = (aSrcH) + (k0);                                             \
        const unsigned* bs_ = (bSrcW) + (size_t)((k0) >> 1) * (ldbW);                   \
        CP16(so_ + (aDstB), as_);                                                       \
        CP16(so_ + (aDstB) + 16, as_ + 8);                                              \
        CP16(so_ + (bDstB), bs_);                                                       \
        CP16(so_ + (bDstB) + 16, bs_ + 4);                                              \
    } while (0)

// GEMM1: g_hidden[e][r][h] = gelu( xh[tok[r]] @ w1p[e] + b1[e] ),  K=DIM
__global__ __launch_bounds__(NTHR, 2)
void gemm1_kernel(const float* __restrict__ b1) {
    int e = blockIdx.z;
    int n = g_cnt[e];
    int row0 = blockIdx.y * BM;
    if (row0 >= n) return;
    int col0 = blockIdx.x * BN;
    const unsigned* Bg = g_w1p + (size_t)e * (DIM / 2) * HID;
    const int ldbW = HID;
    const int KIT = DIM / BK;

    __shared__ __align__(16) unsigned ring[STAGES][STAGE_WORDS];
    __shared__ int toks[BM];

    int tid = threadIdx.x;
    {
        int mg = row0 + tid;
        if (mg >= n) mg = n - 1;
        toks[tid] = g_rows[e * S_TOK + mg];
    }
    __syncthreads();

    int lane = tid & 31, warp = tid >> 5;
    int gid = lane >> 2, tig = lane & 3;
    int wm = (warp & 1) * 64, wn = (warp >> 1) * 64;

    const __half* aSrcH = g_xh + (size_t)toks[tid] * DIM;
    int kp = tid >> 4, nq = (tid & 15) * 8;
    const unsigned* bSrcW = Bg + (size_t)kp * ldbW + col0 + nq;
    uint32_t aDstB = (uint32_t)(tid * ASTRW * 4);
    uint32_t bDstB = (uint32_t)((A_WORDS + kp * BSTRW + nq) * 4);
    uint32_t sbase = smem_u32(ring);

    float acc[4][8][4];
    #pragma unroll
    for (int mt = 0; mt < 4; mt++)
        #pragma unroll
        for (int nt = 0; nt < 8; nt++)
            #pragma unroll
            for (int i = 0; i < 4; i++) acc[mt][nt][i] = 0.f;

    #pragma unroll
    for (int s = 0; s < STAGES - 1; s++) {
        STAGE_CP(s, s * BK, aSrcH, bSrcW, ldbW, aDstB, bDstB, sbase);
        CP_COMMIT();
    }

    for (int it = 0; it < KIT; it++) {
        CP_WAIT2();
        __syncthreads();
        int nxt = it + STAGES - 1;
        if (nxt < KIT)
            STAGE_CP(nxt & (STAGES - 1), nxt * BK, aSrcH, bSrcW, ldbW, aDstB, bDstB, sbase);
        CP_COMMIT();
        compute_stage(ring[it & (STAGES - 1)], wm, wn, gid, tig, acc);
    }

    const float* b1e = b1 + (size_t)e * HID;
    __half* Hb = g_hidden + (size_t)e * S_TOK * HID;
    #pragma unroll
    for (int mt = 0; mt < 4; mt++) {
        #pragma unroll
        for (int half = 0; half < 2; half++) {
            int r = row0 + wm + mt * 16 + gid + half * 8;
            if (r >= n) continue;
            #pragma unroll
            for (int nt = 0; nt < 8; nt++) {
                int c = col0 + wn + nt * 8 + 2 * tig;
                float v0 = acc[mt][nt][half * 2 + 0] + b1e[c];
                float v1 = acc[mt][nt][half * 2 + 1] + b1e[c + 1];
                float t0 = tanhf(0.7978845608028654f * (v0 + 0.044715f * v0 * v0 * v0));
                float t1 = tanhf(0.7978845608028654f * (v1 + 0.044715f * v1 * v1 * v1));
                float g0 = 0.5f * v0 * (1.0f + t0);
                float g1 = 0.5f * v1 * (1.0f + t1);
                *(unsigned*)&Hb[(size_t)r * HID + c] = pack2(g0, g1);
            }
        }
    }
}

// GEMM2: g_y[e][r][d] = g_w[r] * ( g_hidden[e][r] @ w2p[e] + b2[e] ),  K=HID
__global__ __launch_bounds__(NTHR, 2)
void gemm2_kernel(const float* __restrict__ b2) {
    int e = blockIdx.z;
    int n = g_cnt[e];
    int row0 = blockIdx.y * BM;
    if (row0 >= n) return;
    int col0 = blockIdx.x * BN;
    const unsigned* Bg = g_w2p + (size_t)e * (HID / 2) * DIM;
    const int ldbW = DIM;
    const int KIT = HID / BK;

    __shared__ __align__(16) unsigned ring[STAGES][STAGE_WORDS];

    int tid = threadIdx.x;
    int lane = tid & 31, warp = tid >> 5;
    int gid = lane >> 2, tig = lane & 3;
    int wm = (warp & 1) * 64, wn = (warp >> 1) * 64;

    int mg = row0 + tid; if (mg >= n) mg = n - 1;
    const __half* aSrcH = g_hidden + ((size_t)e * S_TOK + mg) * HID;
    int kp = tid >> 4, nq = (tid & 15) * 8;
    const unsigned* bSrcW = Bg + (size_t)kp * ldbW + col0 + nq;
    uint32_t aDstB = (uint32_t)(tid * ASTRW * 4);
    uint32_t bDstB = (uint32_t)((A_WORDS + kp * BSTRW + nq) * 4);
    uint32_t sbase = smem_u32(ring);

    float acc[4][8][4];
    #pragma unroll
    for (int mt = 0; mt < 4; mt++)
        #pragma unroll
        for (int nt = 0; nt < 8; nt++)
            #pragma unroll
            for (int i = 0; i < 4; i++) acc[mt][nt][i] = 0.f;

    #pragma unroll
    for (int s = 0; s < STAGES - 1; s++) {
        STAGE_CP(s, s * BK, aSrcH, bSrcW, ldbW, aDstB, bDstB, sbase);
        CP_COMMIT();
    }

    for (int it = 0; it < KIT; it++) {
        CP_WAIT2();
        __syncthreads();
        int nxt = it + STAGES - 1;
        if (nxt < KIT)
            STAGE_CP(nxt & (STAGES - 1), nxt * BK, aSrcH, bSrcW, ldbW, aDstB, bDstB, sbase);
        CP_COMMIT();
        compute_stage(ring[it & (STAGES - 1)], wm, wn, gid, tig, acc);
    }

    const float* b2e = b2 + (size_t)e * DIM;
    #pragma unroll
    for (int mt = 0; mt < 4; mt++) {
        #pragma unroll
        for (int half = 0; half < 2; half++) {
            int r = row0 + wm + mt * 16 + gid + half * 8;
            if (r >= n) continue;
            float wg = g_w[e * S_TOK + r];
            #pragma unroll
            for (int nt = 0; nt < 8; nt++) {
                int c = col0 + wn + nt * 8 + 2 * tig;
                float2 o;
                o.x = wg * (acc[mt][nt][half * 2 + 0] + b2e[c]);
                o.y = wg * (acc[mt][nt][half * 2 + 1] + b2e[c + 1]);
                *(float2*)&g_y[((size_t)e * S_TOK + r) * DIM + c] = o;
            }
        }
    }
}

// ---------------- deterministic combine (1 block/token, float4) -------------
__global__ void combine_kernel(float* __restrict__ out) {
    int s = blockIdx.x;
    __shared__ int pos[NEXP];
    if (threadIdx.x < NEXP) pos[threadIdx.x] = g_pos[threadIdx.x * S_TOK + s];
    __syncthreads();
    int d = threadIdx.x * 4;
    float4 acc = make_float4(0.f, 0.f, 0.f, 0.f);
    #pragma unroll
    for (int e = 0; e < NEXP; e++) {
        int p = pos[e];
        if (p >= 0) {
            float4 v = *(const float4*)&g_y[((size_t)(e * S_TOK + p)) * DIM + d];
            acc.x += v.x; acc.y += v.y; acc.z += v.z; acc.w += v.w;
        }
    }
    *(float4*)&out[(size_t)s * DIM + d] = acc;
}

// ---------------- launch ----------------
extern "C" void kernel_launch(void* const* d_in, const int* in_sizes, int n_in,
                              void* d_out, int out_size) {
    const float* x  = (const float*)d_in[0];
    const float* gw = (const float*)d_in[1];
    const float* eb = (const float*)d_in[2];
    const float* w1 = (const float*)d_in[3];
    const float* b1 = (const float*)d_in[4];
    const float* w2 = (const float*)d_in[5];
    const float* b2 = (const float*)d_in[6];
    const int*  cap = (const int*)d_in[7];
    float* out = (float*)d_out;

    unsigned *w1p, *w2p;
    cudaGetSymbolAddress((void**)&w1p, g_w1p);
    cudaGetSymbolAddress((void**)&w2p, g_w2p);

    convert_x_kernel<<<(S_TOK * DIM / 8) / 256, 256>>>(x);
    pack_w_kernel<<<(NEXP * (DIM / 2) * (HID / 4)) / 256, 256>>>(w1, w1p, DIM, HID);
    pack_w_kernel<<<(NEXP * (HID / 2) * (DIM / 4)) / 256, 256>>>(w2, w2p, HID, DIM);

    router_kernel<<<S_TOK, 256>>>(x, gw, eb);
    topk_kernel<<<1, 256>>>(cap);
    build_kernel<<<NSCORES / 256, 256>>>();
    gemm1_kernel<<<dim3(HID / BN, S_TOK / BM, NEXP), NTHR>>>(b1);
    gemm2_kernel<<<dim3(DIM / BN, S_TOK / BM, NEXP), NTHR>>>(b2);
    combine_kernel<<<S_TOK, 256>>>(out);
}